// round 1
// baseline (speedup 1.0000x reference)
#include <cuda_runtime.h>
#include <math.h>

#define N_ 32
#define C_ 512
#define P_ 1024
#define K_ 64
#define ALPHAF 100.0f
#define EPSF 1e-12f

// Scratch (device globals; no allocations allowed)
__device__ float g_invn[N_ * P_];          // 1/max(||x[n,:,p]||, eps)
__device__ float g_bias[K_];               // -alpha * ||vocab_k||
__device__ float g_assign[(size_t)N_ * P_ * K_]; // softmax assignments, [n][p][k]
__device__ float g_asum[N_ * K_];          // sum_p a[n,k,p]
__device__ float g_nss[N_];                // per-n global sum of squares (post intra-norm)

// ---------------------------------------------------------------------------
// K0: inv-norm per (n,p); block 0 also computes bias; blocks 1,2 zero scratch.
// ---------------------------------------------------------------------------
__global__ __launch_bounds__(256) void k0_prep(const float* __restrict__ x,
                                               const float* __restrict__ vocabs) {
    int g = blockIdx.x * 256 + threadIdx.x;     // 128 blocks * 256 = 32768 = N*P
    int n = g >> 10;
    int p = g & 1023;
    const float* xp = x + (size_t)n * C_ * P_ + p;
    float ss = 0.0f;
#pragma unroll 8
    for (int c = 0; c < C_; c++) {
        float v = xp[(size_t)c * P_];
        ss = fmaf(v, v, ss);
    }
    g_invn[g] = 1.0f / fmaxf(sqrtf(ss), EPSF);

    if (blockIdx.x == 0) {
        int lane = threadIdx.x & 31;
        int w = threadIdx.x >> 5;
#pragma unroll
        for (int r = 0; r < 8; r++) {
            int k = w * 8 + r;
            float s = 0.0f;
#pragma unroll
            for (int j = 0; j < 16; j++) {
                float v = vocabs[k * C_ + lane + 32 * j];
                s = fmaf(v, v, s);
            }
#pragma unroll
            for (int o = 16; o; o >>= 1) s += __shfl_xor_sync(0xffffffffu, s, o);
            if (lane == 0) g_bias[k] = -ALPHAF * sqrtf(s);
        }
    } else if (blockIdx.x == 1) {
#pragma unroll
        for (int i = 0; i < 8; i++) g_asum[threadIdx.x + 256 * i] = 0.0f;
    } else if (blockIdx.x == 2) {
        if (threadIdx.x < N_) g_nss[threadIdx.x] = 0.0f;
    }
}

// ---------------------------------------------------------------------------
// K1: logits GEMM (K=64 x Ptile=64, loop C) + bias + softmax over K.
// grid (16, 32) = (ptile, n). 256 threads: thread (tx,ty) owns 8k x 2p.
// ---------------------------------------------------------------------------
#define WS_STRIDE 68   // 32 rows of [c][k], padded, 16B-aligned rows
#define LS_STRIDE 65   // 64 rows of [p][k], padded (scalar access)

__global__ __launch_bounds__(256) void k1_assign(const float* __restrict__ x,
                                                 const float* __restrict__ vocabs) {
    __shared__ float sm[32 * WS_STRIDE + 32 * 64];   // 4224 floats; ls aliases (needs 4160)
    float* ws = sm;                // [32][WS_STRIDE]  (w transposed: [c][k])
    float* xs = sm + 32 * WS_STRIDE; // [32][64]       ([c][p])

    int t = threadIdx.x;
    int tx = t & 31, ty = t >> 5;
    int n = blockIdx.y;
    int p0 = blockIdx.x * 64;
    int k0 = ty * 8;
    int pl = tx * 2;

    float acc[8][2];
#pragma unroll
    for (int i = 0; i < 8; i++) { acc[i][0] = 0.0f; acc[i][1] = 0.0f; }

    const float* xb = x + (size_t)n * C_ * P_ + p0;

    for (int c0 = 0; c0 < C_; c0 += 32) {
        // load w chunk transposed: ws[c][k] = 2*alpha*vocab[k][c0+c]
#pragma unroll
        for (int i = 0; i < 8; i++) {
            int e = t + 256 * i;
            int k = e >> 5, c = e & 31;
            ws[c * WS_STRIDE + k] = (2.0f * ALPHAF) * vocabs[k * C_ + c0 + c];
        }
        // load x chunk: xs[c][p]
#pragma unroll
        for (int i = 0; i < 8; i++) {
            int e = t + 256 * i;
            int c = e >> 6, p = e & 63;
            xs[c * 64 + p] = xb[(size_t)(c0 + c) * P_ + p];
        }
        __syncthreads();
#pragma unroll
        for (int cc = 0; cc < 32; cc++) {
            float4 a0 = *(const float4*)(ws + cc * WS_STRIDE + k0);
            float4 a1 = *(const float4*)(ws + cc * WS_STRIDE + k0 + 4);
            float2 b = *(const float2*)(xs + cc * 64 + pl);
            float av[8] = {a0.x, a0.y, a0.z, a0.w, a1.x, a1.y, a1.z, a1.w};
#pragma unroll
            for (int i = 0; i < 8; i++) {
                acc[i][0] = fmaf(av[i], b.x, acc[i][0]);
                acc[i][1] = fmaf(av[i], b.y, acc[i][1]);
            }
        }
        __syncthreads();
    }

    // epilogue: scale by invn[p], add bias, stash logits in shared ls[p][k]
    float inv0 = g_invn[n * P_ + p0 + pl];
    float inv1 = g_invn[n * P_ + p0 + pl + 1];
    float* ls = sm;  // [64][LS_STRIDE]
#pragma unroll
    for (int i = 0; i < 8; i++) {
        float b = g_bias[k0 + i];
        ls[(pl + 0) * LS_STRIDE + k0 + i] = fmaf(acc[i][0], inv0, b);
        ls[(pl + 1) * LS_STRIDE + k0 + i] = fmaf(acc[i][1], inv1, b);
    }
    __syncthreads();

    // softmax over K per column; threads 0..63 each own one p
    if (t < 64) {
        float m = -1e30f;
#pragma unroll
        for (int k = 0; k < 64; k++) m = fmaxf(m, ls[t * LS_STRIDE + k]);
        float s = 0.0f;
#pragma unroll
        for (int k = 0; k < 64; k++) {
            float e = __expf(ls[t * LS_STRIDE + k] - m);
            ls[t * LS_STRIDE + k] = e;
            s += e;
        }
        float r = 1.0f / s;
        float* gp = g_assign + ((size_t)n * P_ + p0 + t) * K_;
#pragma unroll
        for (int k = 0; k < 64; k += 4) {
            float4 o;
            o.x = ls[t * LS_STRIDE + k + 0] * r;
            o.y = ls[t * LS_STRIDE + k + 1] * r;
            o.z = ls[t * LS_STRIDE + k + 2] * r;
            o.w = ls[t * LS_STRIDE + k + 3] * r;
            ls[t * LS_STRIDE + k + 0] = o.x;
            ls[t * LS_STRIDE + k + 1] = o.y;
            ls[t * LS_STRIDE + k + 2] = o.z;
            ls[t * LS_STRIDE + k + 3] = o.w;
            *(float4*)(gp + k) = o;
        }
    }
    __syncthreads();

    // asum partial: threads 0..63, k = t, sum over 64 p-rows
    if (t < 64) {
        float s = 0.0f;
#pragma unroll
        for (int r2 = 0; r2 < 64; r2++) s += ls[r2 * LS_STRIDE + t];
        atomicAdd(&g_asum[n * K_ + t], s);
    }
}

// ---------------------------------------------------------------------------
// K2: vlad GEMM  out[n,k,c] = sum_p (a*invn)[p][k] * x[c][p]  -  asum[k]*vocab[k][c]
// grid (8, 32) = (ctile of 64, n). 256 threads: thread owns 8k x 2c.
// ---------------------------------------------------------------------------
#define XS2_STRIDE 66

__global__ __launch_bounds__(256) void k2_vlad(const float* __restrict__ x,
                                               const float* __restrict__ vocabs,
                                               float* __restrict__ out) {
    __shared__ float as_[32 * 64];          // [p][k]
    __shared__ float xs[32 * XS2_STRIDE];   // [p][c], padded

    int t = threadIdx.x;
    int tx = t & 31, ty = t >> 5;
    int n = blockIdx.y;
    int c0 = blockIdx.x * 64;
    int k0 = ty * 8;
    int cl = tx * 2;

    float acc[8][2];
#pragma unroll
    for (int i = 0; i < 8; i++) { acc[i][0] = 0.0f; acc[i][1] = 0.0f; }

    const float* xb = x + (size_t)n * C_ * P_;
    const float* ab = g_assign + (size_t)n * P_ * K_;
    const float* ib = g_invn + n * P_;

    for (int p0 = 0; p0 < P_; p0 += 32) {
        // a chunk: contiguous copy, scaled by invn[p]
        const float4* a4 = (const float4*)(ab + (size_t)p0 * K_);
#pragma unroll
        for (int i = 0; i < 2; i++) {
            int e4 = t + 256 * i;       // 512 float4s = 2048 floats
            int p = e4 >> 4;            // 16 float4 per 64-float row
            float4 v = a4[e4];
            float inv = ib[p0 + p];
            v.x *= inv; v.y *= inv; v.z *= inv; v.w *= inv;
            *(float4*)(as_ + e4 * 4) = v;
        }
        // x chunk transposed into [p][c]
#pragma unroll
        for (int i = 0; i < 8; i++) {
            int e = t + 256 * i;
            int c = e >> 5, p = e & 31;
            xs[p * XS2_STRIDE + c] = xb[(size_t)(c0 + c) * P_ + p0 + p];
        }
        __syncthreads();
#pragma unroll
        for (int pp = 0; pp < 32; pp++) {
            float4 a0 = *(const float4*)(as_ + pp * 64 + k0);
            float4 a1 = *(const float4*)(as_ + pp * 64 + k0 + 4);
            float2 b = *(const float2*)(xs + pp * XS2_STRIDE + cl);
            float av[8] = {a0.x, a0.y, a0.z, a0.w, a1.x, a1.y, a1.z, a1.w};
#pragma unroll
            for (int i = 0; i < 8; i++) {
                acc[i][0] = fmaf(av[i], b.x, acc[i][0]);
                acc[i][1] = fmaf(av[i], b.y, acc[i][1]);
            }
        }
        __syncthreads();
    }

    // epilogue: subtract asum[k]*vocab[k][c], write unnormalized vlad
#pragma unroll
    for (int i = 0; i < 8; i++) {
        int k = k0 + i;
        float s = g_asum[n * K_ + k];
        float v0 = vocabs[k * C_ + c0 + cl];
        float v1 = vocabs[k * C_ + c0 + cl + 1];
        float2 o;
        o.x = fmaf(-s, v0, acc[i][0]);
        o.y = fmaf(-s, v1, acc[i][1]);
        *(float2*)(out + (size_t)n * (K_ * C_) + (size_t)k * C_ + c0 + cl) = o;
    }
}

// ---------------------------------------------------------------------------
// K3a: intra-normalize each [n,k,:] row (512 elems), accumulate per-n sumsq
// grid (64, 32), 256 threads (2 elems each).
// ---------------------------------------------------------------------------
__global__ __launch_bounds__(256) void k3a_intra(float* __restrict__ out) {
    int n = blockIdx.y, k = blockIdx.x, t = threadIdx.x;
    float* row = out + (size_t)n * (K_ * C_) + (size_t)k * C_;
    float2 v = *(float2*)(row + t * 2);
    float ss = v.x * v.x + v.y * v.y;
#pragma unroll
    for (int o = 16; o; o >>= 1) ss += __shfl_xor_sync(0xffffffffu, ss, o);
    __shared__ float wsum[8];
    if ((t & 31) == 0) wsum[t >> 5] = ss;
    __syncthreads();
    float tot = wsum[0] + wsum[1] + wsum[2] + wsum[3] +
                wsum[4] + wsum[5] + wsum[6] + wsum[7];
    float rinv = 1.0f / fmaxf(sqrtf(tot), EPSF);
    v.x *= rinv; v.y *= rinv;
    *(float2*)(row + t * 2) = v;
    if (t == 0) atomicAdd(&g_nss[n], tot * rinv * rinv);
}

// ---------------------------------------------------------------------------
// K3b: final global normalization per n (in place).
// ---------------------------------------------------------------------------
__global__ __launch_bounds__(256) void k3b_final(float* __restrict__ out) {
    int g4 = blockIdx.x * 256 + threadIdx.x;   // 1024 blocks * 256 float4 = 1M floats
    int n = (g4 * 4) >> 15;                    // 32768 floats per n
    float r = 1.0f / fmaxf(sqrtf(g_nss[n]), EPSF);
    float4 v = ((float4*)out)[g4];
    v.x *= r; v.y *= r; v.z *= r; v.w *= r;
    ((float4*)out)[g4] = v;
}

// ---------------------------------------------------------------------------
extern "C" void kernel_launch(void* const* d_in, const int* in_sizes, int n_in,
                              void* d_out, int out_size) {
    const float* x = (const float*)d_in[0];
    const float* vocabs = (const float*)d_in[1];
    if (n_in >= 2 && in_sizes[0] == K_ * C_ && in_sizes[1] == N_ * C_ * P_) {
        // defensive: inputs swapped
        vocabs = (const float*)d_in[0];
        x = (const float*)d_in[1];
    }
    float* out = (float*)d_out;

    k0_prep<<<128, 256>>>(x, vocabs);
    k1_assign<<<dim3(16, 32), 256>>>(x, vocabs);
    k2_vlad<<<dim3(8, 32), 256>>>(x, vocabs, out);
    k3a_intra<<<dim3(64, 32), 256>>>(out);
    k3b_final<<<1024, 256>>>(out);
}